// round 3
// baseline (speedup 1.0000x reference)
#include <cuda_runtime.h>
#include <cuda_bf16.h>

// ---------------- problem constants ----------------
#define W_IMG 135
#define H_IMG 240
#define NPIX (W_IMG * H_IMG)
#define NF 1000
#define NV 600
#define TW 16            // tile width (pixels)
#define TH 8             // tile height (pixels)
#define TX 9             // ceil(135/16)
#define TY 30            // 240/8
#define NT (TX * TY)     // 270 tiles
#define NSLICE 8         // face-parallel slices per tile
#define CHUNK 128
#define BLUR_F 9.21024036697585e-04f
#define INV_SIGMA 10000.0f
#define RB 0.0315f       // > sqrt(BLUR) = 0.0303

// ---------------- device scratch (no allocations allowed) ----------------
__device__ float4 g_face[NF * 3];        // {ax,ay,e0x,e0y} {e1x,e1y,e2x,e2y} {r0,r1,r2,-}
__device__ int    g_tileCount[NT];
__device__ int    g_tileList[NT * NF];
__device__ float  g_Spart[NSLICE * NT * (TW * TH)];
__device__ float  g_lossAcc;
__device__ int    g_ticket;

// ---------------- prep: zero + project + bin, one block ----------------
__global__ void __launch_bounds__(256)
sil_prep_kernel(const float* __restrict__ verts, const int* __restrict__ faces) {
    __shared__ float svx[NV], svy[NV], svz[NV];
    int tid = threadIdx.x;

    for (int i = tid; i < NT; i += 256) g_tileCount[i] = 0;
    if (tid == 0) { g_lossAcc = 0.0f; g_ticket = 0; }

    for (int i = tid; i < NV; i += 256) {
        float x = verts[3 * i + 0];
        float y = verts[3 * i + 1];
        float z = verts[3 * i + 2];
        float inv = 1.0f / fmaxf(z, 1e-6f);
        svx[i] = (1000.0f * (-x) * inv + 512.0f) * (1.0f / 1024.0f) * (float)W_IMG;
        svy[i] = (1000.0f * (-y) * inv + 512.0f) * (1.0f / 1024.0f) * (float)H_IMG;
        svz[i] = z;
    }
    __syncthreads();

    for (int f = tid; f < NF; f += 256) {
        int i0 = faces[3 * f + 0];
        int i1 = faces[3 * f + 1];
        int i2 = faces[3 * f + 2];
        float ax = svx[i0], ay = svy[i0];
        float bx = svx[i1], by = svy[i1];
        float cx = svx[i2], cy = svy[i2];
        float tz = (svz[i0] + svz[i1] + svz[i2]) * (1.0f / 3.0f);
        if (!(tz > 1e-6f)) continue;   // valid=false everywhere -> zero contribution

        float e0x = bx - ax, e0y = by - ay;
        float e1x = cx - bx, e1y = cy - by;
        float e2x = ax - cx, e2y = ay - cy;
        float r0 = 1.0f / (e0x * e0x + e0y * e0y + 1e-12f);
        float r1 = 1.0f / (e1x * e1x + e1y * e1y + 1e-12f);
        float r2 = 1.0f / (e2x * e2x + e2y * e2y + 1e-12f);
        g_face[3 * f + 0] = make_float4(ax, ay, e0x, e0y);
        g_face[3 * f + 1] = make_float4(e1x, e1y, e2x, e2y);
        g_face[3 * f + 2] = make_float4(r0, r1, r2, 0.0f);

        // exact culling: contribution is zero > sqrt(BLUR) away from triangle
        float minx = fminf(ax, fminf(bx, cx)) - RB;
        float maxx = fmaxf(ax, fmaxf(bx, cx)) + RB;
        float miny = fminf(ay, fminf(by, cy)) - RB;
        float maxy = fmaxf(ay, fmaxf(by, cy)) + RB;
        int ixlo = max(0,         (int)floorf(minx - 0.5f));
        int ixhi = min(W_IMG - 1, (int)ceilf (maxx - 0.5f));
        int iylo = max(0,         (int)floorf(miny - 0.5f));
        int iyhi = min(H_IMG - 1, (int)ceilf (maxy - 0.5f));
        if (ixlo > ixhi || iylo > iyhi) continue;
        int txlo = ixlo / TW, txhi = ixhi / TW;
        int tylo = iylo / TH, tyhi = iyhi / TH;
        for (int ty = tylo; ty <= tyhi; ty++) {
            for (int tx = txlo; tx <= txhi; tx++) {
                int t = ty * TX + tx;
                int s = atomicAdd(&g_tileCount[t], 1);
                g_tileList[t * NF + s] = f;
            }
        }
    }
}

// ---------------- render: grid = NT * NSLICE, face-parallel partial sums ----------------
__global__ void __launch_bounds__(TW * TH)
sil_render_kernel() {
    __shared__ float4 sF[CHUNK * 3];

    int b   = blockIdx.x;
    int t   = b % NT;          // interleave: heavy tiles spread across SMs
    int s   = b / NT;          // slice id
    int tid = threadIdx.x;
    int tx  = t % TX, ty = t / TX;
    float px = (float)(tx * TW + (tid % TW)) + 0.5f;
    float py = (float)(ty * TH + (tid / TW)) + 0.5f;

    int n = g_tileCount[t];
    float S = 0.0f;

    for (int base = s; base < n; base += NSLICE * CHUNK) {
        // faces handled this chunk: base + k*NSLICE, k in [0, m)
        int m = min(CHUNK, (n - base + NSLICE - 1) / NSLICE);
        __syncthreads();
        if (tid < m) {
            int f = g_tileList[t * NF + base + tid * NSLICE];
            sF[tid * 3 + 0] = g_face[f * 3 + 0];
            sF[tid * 3 + 1] = g_face[f * 3 + 1];
            sF[tid * 3 + 2] = g_face[f * 3 + 2];
        }
        __syncthreads();
        #pragma unroll 2
        for (int j = 0; j < m; j++) {
            float4 A = sF[j * 3 + 0];   // ax, ay, e0x, e0y
            float4 B = sF[j * 3 + 1];   // e1x, e1y, e2x, e2y
            float4 R = sF[j * 3 + 2];   // r0, r1, r2

            float apx = px - A.x, apy = py - A.y;
            float bpx = apx - A.z, bpy = apy - A.w;
            float cpx = bpx - B.x, cpy = bpy - B.y;

            float c0 = A.z * apy - A.w * apx;
            float c1 = B.x * bpy - B.y * bpx;
            float c2 = B.z * cpy - B.w * cpx;
            bool pos = (c0 >= 0.0f) & (c1 >= 0.0f) & (c2 >= 0.0f);
            bool neg = (c0 <= 0.0f) & (c1 <= 0.0f) & (c2 <= 0.0f);

            float t0 = fminf(fmaxf((apx * A.z + apy * A.w) * R.x, 0.0f), 1.0f);
            float t1 = fminf(fmaxf((bpx * B.x + bpy * B.y) * R.y, 0.0f), 1.0f);
            float t2 = fminf(fmaxf((cpx * B.z + cpy * B.w) * R.z, 0.0f), 1.0f);
            float dx0 = apx - t0 * A.z, dy0 = apy - t0 * A.w;
            float dx1 = bpx - t1 * B.x, dy1 = bpy - t1 * B.y;
            float dx2 = cpx - t2 * B.z, dy2 = cpy - t2 * B.w;
            float d0 = dx0 * dx0 + dy0 * dy0;
            float d1 = dx1 * dx1 + dy1 * dy1;
            float d2 = dx2 * dx2 + dy2 * dy2;
            float dmin = fminf(d0, fminf(d1, d2));

            bool inside = pos | neg;
            if (inside | (dmin <= BLUR_F)) {
                float x = inside ? dmin * INV_SIGMA : -dmin * INV_SIGMA;
                // log1p(-sigmoid(x)) = -softplus(x)
                float sp = fmaxf(x, 0.0f) + __logf(1.0f + __expf(-fabsf(x)));
                S -= sp;
            }
        }
    }

    g_Spart[b * (TW * TH) + tid] = S;
}

// ---------------- finalize: combine slices, alpha, loss, last-block writes loss ----------------
__global__ void __launch_bounds__(TW * TH)
sil_finalize_kernel(const float* __restrict__ gt, float* __restrict__ out, int sil_off) {
    __shared__ float sRed[4];
    int t   = blockIdx.x;
    int tid = threadIdx.x;
    int ix  = (t % TX) * TW + (tid % TW);
    int iy  = (t / TX) * TH + (tid / TW);

    float S = 0.0f;
    #pragma unroll
    for (int s = 0; s < NSLICE; s++)
        S += g_Spart[(s * NT + t) * (TW * TH) + tid];

    float alpha = 1.0f - __expf(S);
    float diff = 0.0f;
    if (ix < W_IMG) {
        out[sil_off + iy * W_IMG + ix] = alpha;
        diff = fabsf(alpha - gt[iy * W_IMG + ix]);
    }
    #pragma unroll
    for (int o = 16; o > 0; o >>= 1)
        diff += __shfl_down_sync(0xFFFFFFFFu, diff, o);
    if ((tid & 31) == 0) sRed[tid >> 5] = diff;
    __syncthreads();
    if (tid == 0 && sil_off) {
        atomicAdd(&g_lossAcc, sRed[0] + sRed[1] + sRed[2] + sRed[3]);
        __threadfence();
        int done = atomicAdd(&g_ticket, 1);
        if (done == NT - 1) {
            float total = atomicAdd(&g_lossAcc, 0.0f);  // coherent read of final sum
            out[0] = total * (1.0f / (float)NPIX);
        }
    }
}

// ---------------- launch ----------------
extern "C" void kernel_launch(void* const* d_in, const int* in_sizes, int n_in,
                              void* d_out, int out_size) {
    const float* verts = nullptr;
    const float* gt    = nullptr;
    const int*   faces = nullptr;
    for (int i = 0; i < n_in; i++) {
        if (in_sizes[i] == NV * 3)  verts = (const float*)d_in[i];
        else if (in_sizes[i] == NPIX) gt  = (const float*)d_in[i];
        else if (in_sizes[i] == NF * 3) faces = (const int*)d_in[i];
    }
    float* out = (float*)d_out;
    int sil_off = (out_size > NPIX) ? 1 : 0;   // [loss, sil...] vs [sil...]

    sil_prep_kernel<<<1, 256>>>(verts, faces);
    sil_render_kernel<<<NT * NSLICE, TW * TH>>>();
    sil_finalize_kernel<<<NT, TW * TH>>>(gt, out, sil_off);
}

// round 4
// speedup vs baseline: 2.5756x; 2.5756x over previous
#include <cuda_runtime.h>
#include <cuda_bf16.h>

// ---------------- problem constants ----------------
#define W_IMG 135
#define H_IMG 240
#define NPIX (W_IMG * H_IMG)
#define NF 1000
#define NV 600
#define TW 16            // tile width (pixels)
#define TH 8             // tile height (pixels)
#define TX 9             // ceil(135/16)
#define TY 30            // 240/8
#define NT (TX * TY)     // 270 tiles
#define NSLICE 8         // face-parallel slices per tile
#define CHUNK 128
#define BLUR_F 9.21024036697585e-04f
#define INV_SIGMA 10000.0f
#define RB 0.0315f       // > sqrt(BLUR) = 0.0303

// ---------------- device scratch (no allocations allowed) ----------------
__device__ float  g_vx[NV];
__device__ float  g_vy[NV];
__device__ float  g_vz[NV];
__device__ float4 g_face[NF * 3];        // {ax,ay,e0x,e0y} {e1x,e1y,e2x,e2y} {r0,r1,r2,-}
__device__ int    g_tileCount[NT];
__device__ int    g_tileList[NT * NF];
__device__ float  g_Spart[NSLICE * NT * (TW * TH)];
__device__ float  g_lossAcc;
__device__ int    g_ticket;

// ---------------- project verts (block 0 also zeroes counters) ----------------
__global__ void __launch_bounds__(256)
sil_project_kernel(const float* __restrict__ verts) {
    int tid = threadIdx.x;
    if (blockIdx.x == 0) {
        for (int i = tid; i < NT; i += 256) g_tileCount[i] = 0;
        if (tid == 0) { g_lossAcc = 0.0f; g_ticket = 0; }
    }
    int i = blockIdx.x * 256 + tid;
    if (i >= NV) return;
    float x = verts[3 * i + 0];
    float y = verts[3 * i + 1];
    float z = verts[3 * i + 2];
    float inv = 1.0f / fmaxf(z, 1e-6f);
    g_vx[i] = (1000.0f * (-x) * inv + 512.0f) * (1.0f / 1024.0f) * (float)W_IMG;
    g_vy[i] = (1000.0f * (-y) * inv + 512.0f) * (1.0f / 1024.0f) * (float)H_IMG;
    g_vz[i] = z;
}

// ---------------- bin faces into tiles ----------------
__global__ void __launch_bounds__(256)
sil_bin_kernel(const int* __restrict__ faces) {
    int f = blockIdx.x * 256 + threadIdx.x;
    if (f >= NF) return;
    int i0 = faces[3 * f + 0];
    int i1 = faces[3 * f + 1];
    int i2 = faces[3 * f + 2];
    float ax = g_vx[i0], ay = g_vy[i0];
    float bx = g_vx[i1], by = g_vy[i1];
    float cx = g_vx[i2], cy = g_vy[i2];
    float tz = (g_vz[i0] + g_vz[i1] + g_vz[i2]) * (1.0f / 3.0f);
    if (!(tz > 1e-6f)) return;   // valid=false everywhere -> zero contribution

    float e0x = bx - ax, e0y = by - ay;
    float e1x = cx - bx, e1y = cy - by;
    float e2x = ax - cx, e2y = ay - cy;
    float r0 = 1.0f / (e0x * e0x + e0y * e0y + 1e-12f);
    float r1 = 1.0f / (e1x * e1x + e1y * e1y + 1e-12f);
    float r2 = 1.0f / (e2x * e2x + e2y * e2y + 1e-12f);
    g_face[3 * f + 0] = make_float4(ax, ay, e0x, e0y);
    g_face[3 * f + 1] = make_float4(e1x, e1y, e2x, e2y);
    g_face[3 * f + 2] = make_float4(r0, r1, r2, 0.0f);

    // exact culling: contribution is zero > sqrt(BLUR) away from triangle
    float minx = fminf(ax, fminf(bx, cx)) - RB;
    float maxx = fmaxf(ax, fmaxf(bx, cx)) + RB;
    float miny = fminf(ay, fminf(by, cy)) - RB;
    float maxy = fmaxf(ay, fmaxf(by, cy)) + RB;
    int ixlo = max(0,         (int)floorf(minx - 0.5f));
    int ixhi = min(W_IMG - 1, (int)ceilf (maxx - 0.5f));
    int iylo = max(0,         (int)floorf(miny - 0.5f));
    int iyhi = min(H_IMG - 1, (int)ceilf (maxy - 0.5f));
    if (ixlo > ixhi || iylo > iyhi) return;
    int txlo = ixlo / TW, txhi = ixhi / TW;
    int tylo = iylo / TH, tyhi = iyhi / TH;
    for (int ty = tylo; ty <= tyhi; ty++) {
        for (int tx = txlo; tx <= txhi; tx++) {
            int t = ty * TX + tx;
            int s = atomicAdd(&g_tileCount[t], 1);
            g_tileList[t * NF + s] = f;
        }
    }
}

// ---------------- render: grid = NT * NSLICE, face-parallel partial sums ----------------
__global__ void __launch_bounds__(TW * TH)
sil_render_kernel() {
    __shared__ float4 sF[CHUNK * 3];

    int b   = blockIdx.x;
    int t   = b % NT;          // interleave: heavy tiles spread across SMs
    int s   = b / NT;          // slice id
    int tid = threadIdx.x;
    int tx  = t % TX, ty = t / TX;
    float px = (float)(tx * TW + (tid % TW)) + 0.5f;
    float py = (float)(ty * TH + (tid / TW)) + 0.5f;

    int n = g_tileCount[t];
    float S = 0.0f;

    for (int base = s; base < n; base += NSLICE * CHUNK) {
        // faces handled this chunk: base + k*NSLICE, k in [0, m)
        int m = min(CHUNK, (n - base + NSLICE - 1) / NSLICE);
        __syncthreads();
        if (tid < m) {
            int f = g_tileList[t * NF + base + tid * NSLICE];
            sF[tid * 3 + 0] = g_face[f * 3 + 0];
            sF[tid * 3 + 1] = g_face[f * 3 + 1];
            sF[tid * 3 + 2] = g_face[f * 3 + 2];
        }
        __syncthreads();
        #pragma unroll 2
        for (int j = 0; j < m; j++) {
            float4 A = sF[j * 3 + 0];   // ax, ay, e0x, e0y
            float4 B = sF[j * 3 + 1];   // e1x, e1y, e2x, e2y
            float4 R = sF[j * 3 + 2];   // r0, r1, r2

            float apx = px - A.x, apy = py - A.y;
            float bpx = apx - A.z, bpy = apy - A.w;
            float cpx = bpx - B.x, cpy = bpy - B.y;

            float c0 = A.z * apy - A.w * apx;
            float c1 = B.x * bpy - B.y * bpx;
            float c2 = B.z * cpy - B.w * cpx;
            bool pos = (c0 >= 0.0f) & (c1 >= 0.0f) & (c2 >= 0.0f);
            bool neg = (c0 <= 0.0f) & (c1 <= 0.0f) & (c2 <= 0.0f);

            float t0 = fminf(fmaxf((apx * A.z + apy * A.w) * R.x, 0.0f), 1.0f);
            float t1 = fminf(fmaxf((bpx * B.x + bpy * B.y) * R.y, 0.0f), 1.0f);
            float t2 = fminf(fmaxf((cpx * B.z + cpy * B.w) * R.z, 0.0f), 1.0f);
            float dx0 = apx - t0 * A.z, dy0 = apy - t0 * A.w;
            float dx1 = bpx - t1 * B.x, dy1 = bpy - t1 * B.y;
            float dx2 = cpx - t2 * B.z, dy2 = cpy - t2 * B.w;
            float d0 = dx0 * dx0 + dy0 * dy0;
            float d1 = dx1 * dx1 + dy1 * dy1;
            float d2 = dx2 * dx2 + dy2 * dy2;
            float dmin = fminf(d0, fminf(d1, d2));

            bool inside = pos | neg;
            if (inside | (dmin <= BLUR_F)) {
                float x = inside ? dmin * INV_SIGMA : -dmin * INV_SIGMA;
                // log1p(-sigmoid(x)) = -softplus(x)
                float sp = fmaxf(x, 0.0f) + __logf(1.0f + __expf(-fabsf(x)));
                S -= sp;
            }
        }
    }

    g_Spart[b * (TW * TH) + tid] = S;
}

// ---------------- finalize: combine slices, alpha, loss, last-block writes loss ----------------
__global__ void __launch_bounds__(TW * TH)
sil_finalize_kernel(const float* __restrict__ gt, float* __restrict__ out, int sil_off) {
    __shared__ float sRed[4];
    int t   = blockIdx.x;
    int tid = threadIdx.x;
    int ix  = (t % TX) * TW + (tid % TW);
    int iy  = (t / TX) * TH + (tid / TW);

    float S = 0.0f;
    #pragma unroll
    for (int s = 0; s < NSLICE; s++)
        S += g_Spart[(s * NT + t) * (TW * TH) + tid];

    float alpha = 1.0f - __expf(S);
    float diff = 0.0f;
    if (ix < W_IMG) {
        out[sil_off + iy * W_IMG + ix] = alpha;
        diff = fabsf(alpha - gt[iy * W_IMG + ix]);
    }
    #pragma unroll
    for (int o = 16; o > 0; o >>= 1)
        diff += __shfl_down_sync(0xFFFFFFFFu, diff, o);
    if ((tid & 31) == 0) sRed[tid >> 5] = diff;
    __syncthreads();
    if (tid == 0 && sil_off) {
        atomicAdd(&g_lossAcc, sRed[0] + sRed[1] + sRed[2] + sRed[3]);
        __threadfence();
        int done = atomicAdd(&g_ticket, 1);
        if (done == NT - 1) {
            float total = atomicAdd(&g_lossAcc, 0.0f);  // coherent read of final sum
            out[0] = total * (1.0f / (float)NPIX);
        }
    }
}

// ---------------- launch ----------------
extern "C" void kernel_launch(void* const* d_in, const int* in_sizes, int n_in,
                              void* d_out, int out_size) {
    const float* verts = nullptr;
    const float* gt    = nullptr;
    const int*   faces = nullptr;
    for (int i = 0; i < n_in; i++) {
        if (in_sizes[i] == NV * 3)  verts = (const float*)d_in[i];
        else if (in_sizes[i] == NPIX) gt  = (const float*)d_in[i];
        else if (in_sizes[i] == NF * 3) faces = (const int*)d_in[i];
    }
    float* out = (float*)d_out;
    int sil_off = (out_size > NPIX) ? 1 : 0;   // [loss, sil...] vs [sil...]

    sil_project_kernel<<<(NV + 255) / 256, 256>>>(verts);
    sil_bin_kernel<<<(NF + 255) / 256, 256>>>(faces);
    sil_render_kernel<<<NT * NSLICE, TW * TH>>>();
    sil_finalize_kernel<<<NT, TW * TH>>>(gt, out, sil_off);
}

// round 5
// speedup vs baseline: 2.7509x; 1.0680x over previous
#include <cuda_runtime.h>
#include <cuda_bf16.h>

// ---------------- problem constants ----------------
#define W_IMG 135
#define H_IMG 240
#define NPIX (W_IMG * H_IMG)
#define NF 1000
#define NV 600
#define TW 16            // tile width (pixels)
#define TH 8             // tile height (pixels)
#define TX 9             // ceil(135/16)
#define TY 30            // 240/8
#define NT (TX * TY)     // 270 tiles
#define NSLICE 8         // face-parallel slices per tile
#define CHUNK 128
#define BLUR_F 9.21024036697585e-04f
#define INV_SIGMA 10000.0f
#define RB 0.0315f       // > sqrt(BLUR) = 0.0303

// ---------------- device scratch (no allocations; zero-initialized) ----------------
__device__ float4 g_face[NF * 3];        // {ax,ay,e0x,e0y} {e1x,e1y,e2x,e2y} {r0,r1,r2,-}
__device__ int    g_tileCount[NT];       // must be 0 at kernel entry (self-resetting)
__device__ int    g_tileTicket[NT];      // must be 0 at kernel entry (self-resetting)
__device__ int    g_tileList[NT * NF];
__device__ float  g_Spart[NSLICE * NT * (TW * TH)];
__device__ float  g_lossAcc;             // 0 at entry (self-resetting)
__device__ int    g_ticket;              // 0 at entry (self-resetting)

// ---------------- bin: inline projection + face setup + tile binning ----------------
__global__ void __launch_bounds__(256)
sil_bin_kernel(const float* __restrict__ verts, const int* __restrict__ faces) {
    int f = blockIdx.x * 256 + threadIdx.x;
    if (f >= NF) return;
    int i0 = faces[3 * f + 0];
    int i1 = faces[3 * f + 1];
    int i2 = faces[3 * f + 2];

    // inline projection of the 3 vertices (R = diag(-1,-1,1))
    float x0 = verts[3 * i0], y0 = verts[3 * i0 + 1], z0 = verts[3 * i0 + 2];
    float x1 = verts[3 * i1], y1 = verts[3 * i1 + 1], z1 = verts[3 * i1 + 2];
    float x2 = verts[3 * i2], y2 = verts[3 * i2 + 1], z2 = verts[3 * i2 + 2];

    float tz = (z0 + z1 + z2) * (1.0f / 3.0f);
    if (!(tz > 1e-6f)) return;   // valid=false everywhere -> zero contribution

    const float SX = (1.0f / 1024.0f) * (float)W_IMG;
    const float SY = (1.0f / 1024.0f) * (float)H_IMG;
    float inv0 = 1.0f / fmaxf(z0, 1e-6f);
    float inv1 = 1.0f / fmaxf(z1, 1e-6f);
    float inv2 = 1.0f / fmaxf(z2, 1e-6f);
    float ax = (1000.0f * (-x0) * inv0 + 512.0f) * SX;
    float ay = (1000.0f * (-y0) * inv0 + 512.0f) * SY;
    float bx = (1000.0f * (-x1) * inv1 + 512.0f) * SX;
    float by = (1000.0f * (-y1) * inv1 + 512.0f) * SY;
    float cx = (1000.0f * (-x2) * inv2 + 512.0f) * SX;
    float cy = (1000.0f * (-y2) * inv2 + 512.0f) * SY;

    float e0x = bx - ax, e0y = by - ay;
    float e1x = cx - bx, e1y = cy - by;
    float e2x = ax - cx, e2y = ay - cy;
    float r0 = 1.0f / (e0x * e0x + e0y * e0y + 1e-12f);
    float r1 = 1.0f / (e1x * e1x + e1y * e1y + 1e-12f);
    float r2 = 1.0f / (e2x * e2x + e2y * e2y + 1e-12f);
    g_face[3 * f + 0] = make_float4(ax, ay, e0x, e0y);
    g_face[3 * f + 1] = make_float4(e1x, e1y, e2x, e2y);
    g_face[3 * f + 2] = make_float4(r0, r1, r2, 0.0f);

    // exact culling: contribution is zero > sqrt(BLUR) away from triangle
    float minx = fminf(ax, fminf(bx, cx)) - RB;
    float maxx = fmaxf(ax, fmaxf(bx, cx)) + RB;
    float miny = fminf(ay, fminf(by, cy)) - RB;
    float maxy = fmaxf(ay, fmaxf(by, cy)) + RB;
    int ixlo = max(0,         (int)floorf(minx - 0.5f));
    int ixhi = min(W_IMG - 1, (int)ceilf (maxx - 0.5f));
    int iylo = max(0,         (int)floorf(miny - 0.5f));
    int iyhi = min(H_IMG - 1, (int)ceilf (maxy - 0.5f));
    if (ixlo > ixhi || iylo > iyhi) return;
    int txlo = ixlo / TW, txhi = ixhi / TW;
    int tylo = iylo / TH, tyhi = iyhi / TH;
    for (int ty = tylo; ty <= tyhi; ty++) {
        for (int tx = txlo; tx <= txhi; tx++) {
            int t = ty * TX + tx;
            int s = atomicAdd(&g_tileCount[t], 1);
            g_tileList[t * NF + s] = f;
        }
    }
}

// ---------------- render + fused finalize (threadfence reduction) ----------------
__global__ void __launch_bounds__(TW * TH)
sil_render_kernel(const float* __restrict__ gt, float* __restrict__ out, int sil_off) {
    __shared__ float4 sF[CHUNK * 3];
    __shared__ float  sRed[4];
    __shared__ int    sLast;

    int b   = blockIdx.x;
    int t   = b % NT;          // interleave: heavy tiles spread across SMs
    int s   = b / NT;          // slice id
    int tid = threadIdx.x;
    int tx  = t % TX, ty = t / TX;
    int ix  = tx * TW + (tid % TW);
    int iy  = ty * TH + (tid / TW);
    float px = (float)ix + 0.5f;
    float py = (float)iy + 0.5f;

    int n = g_tileCount[t];
    float S = 0.0f;

    // NSLICE=8 => per-slice faces <= ceil(NF/NSLICE)=125 <= CHUNK: single pass
    {
        int base = s;
        int m = (n > base) ? min(CHUNK, (n - base + NSLICE - 1) / NSLICE) : 0;
        if (tid < m) {
            int f = g_tileList[t * NF + base + tid * NSLICE];
            sF[tid * 3 + 0] = g_face[f * 3 + 0];
            sF[tid * 3 + 1] = g_face[f * 3 + 1];
            sF[tid * 3 + 2] = g_face[f * 3 + 2];
        }
        __syncthreads();
        #pragma unroll 2
        for (int j = 0; j < m; j++) {
            float4 A = sF[j * 3 + 0];   // ax, ay, e0x, e0y
            float4 B = sF[j * 3 + 1];   // e1x, e1y, e2x, e2y
            float4 R = sF[j * 3 + 2];   // r0, r1, r2

            float apx = px - A.x, apy = py - A.y;
            float bpx = apx - A.z, bpy = apy - A.w;
            float cpx = bpx - B.x, cpy = bpy - B.y;

            float c0 = A.z * apy - A.w * apx;
            float c1 = B.x * bpy - B.y * bpx;
            float c2 = B.z * cpy - B.w * cpx;
            bool pos = (c0 >= 0.0f) & (c1 >= 0.0f) & (c2 >= 0.0f);
            bool neg = (c0 <= 0.0f) & (c1 <= 0.0f) & (c2 <= 0.0f);

            float t0 = fminf(fmaxf((apx * A.z + apy * A.w) * R.x, 0.0f), 1.0f);
            float t1 = fminf(fmaxf((bpx * B.x + bpy * B.y) * R.y, 0.0f), 1.0f);
            float t2 = fminf(fmaxf((cpx * B.z + cpy * B.w) * R.z, 0.0f), 1.0f);
            float dx0 = apx - t0 * A.z, dy0 = apy - t0 * A.w;
            float dx1 = bpx - t1 * B.x, dy1 = bpy - t1 * B.y;
            float dx2 = cpx - t2 * B.z, dy2 = cpy - t2 * B.w;
            float d0 = dx0 * dx0 + dy0 * dy0;
            float d1 = dx1 * dx1 + dy1 * dy1;
            float d2 = dx2 * dx2 + dy2 * dy2;
            float dmin = fminf(d0, fminf(d1, d2));

            bool inside = pos | neg;
            if (inside | (dmin <= BLUR_F)) {
                float x = inside ? dmin * INV_SIGMA : -dmin * INV_SIGMA;
                // log1p(-sigmoid(x)) = -softplus(x)
                float sp = fmaxf(x, 0.0f) + __logf(1.0f + __expf(-fabsf(x)));
                S -= sp;
            }
        }
    }

    g_Spart[b * (TW * TH) + tid] = S;

    // ----- per-tile ticket: last-arriving block finalizes this tile -----
    __threadfence();
    __syncthreads();
    if (tid == 0)
        sLast = (atomicAdd(&g_tileTicket[t], 1) == NSLICE - 1) ? 1 : 0;
    __syncthreads();
    if (!sLast) return;

    // all other slice blocks of tile t have published their Spart
    float Ssum = 0.0f;
    #pragma unroll
    for (int sl = 0; sl < NSLICE; sl++)
        Ssum += g_Spart[(sl * NT + t) * (TW * TH) + tid];

    float alpha = 1.0f - __expf(Ssum);
    float diff = 0.0f;
    if (ix < W_IMG) {
        out[sil_off + iy * W_IMG + ix] = alpha;
        diff = fabsf(alpha - gt[iy * W_IMG + ix]);
    }
    #pragma unroll
    for (int o = 16; o > 0; o >>= 1)
        diff += __shfl_down_sync(0xFFFFFFFFu, diff, o);
    if ((tid & 31) == 0) sRed[tid >> 5] = diff;
    __syncthreads();

    if (tid == 0) {
        // reset per-tile state for the next graph replay (safe: all readers done)
        g_tileTicket[t] = 0;
        g_tileCount[t]  = 0;

        atomicAdd(&g_lossAcc, sRed[0] + sRed[1] + sRed[2] + sRed[3]);
        __threadfence();
        int done = atomicAdd(&g_ticket, 1);
        if (done == NT - 1) {
            float total = atomicExch(&g_lossAcc, 0.0f);   // read + reset
            if (sil_off) out[0] = total * (1.0f / (float)NPIX);
            g_ticket = 0;
        }
    }
}

// ---------------- launch ----------------
extern "C" void kernel_launch(void* const* d_in, const int* in_sizes, int n_in,
                              void* d_out, int out_size) {
    const float* verts = nullptr;
    const float* gt    = nullptr;
    const int*   faces = nullptr;
    for (int i = 0; i < n_in; i++) {
        if (in_sizes[i] == NV * 3)  verts = (const float*)d_in[i];
        else if (in_sizes[i] == NPIX) gt  = (const float*)d_in[i];
        else if (in_sizes[i] == NF * 3) faces = (const int*)d_in[i];
    }
    float* out = (float*)d_out;
    int sil_off = (out_size > NPIX) ? 1 : 0;   // [loss, sil...] vs [sil...]

    sil_bin_kernel<<<(NF + 255) / 256, 256>>>(verts, faces);
    sil_render_kernel<<<NT * NSLICE, TW * TH>>>(gt, out, sil_off);
}